// round 10
// baseline (speedup 1.0000x reference)
#include <cuda_runtime.h>

// Problem constants
#define Bb 512
#define Ss 1024
#define Ff 64
#define Ll 128
#define Gg 512    // 4*L
#define BT 4      // batch rows per CTA
#define CRS 8     // K floats per (gate, K-slice) held in registers
#define NKK 6     // smem float4 chunks per (gate, K-slice): 24 floats
#define SLICE 36  // padded K-slice stride in h smem (32 + 4)
#define HP 148    // padded h row stride (4*SLICE + 4)

typedef unsigned long long ull;

// ------------------------- device scratch -------------------------
__device__ float g_gx[(size_t)Bb * Ss * Gg];    // x-proj + enc bias, slots [i,f,g,o] per latent (1 GB)
__device__ float g_hall[(size_t)Bb * Ss * Ll];  // decoder h states (256 MB)
__device__ float g_weff[Gg * Ll];               // W_hh_dec + W_ih_dec @ W_dense
__device__ float g_benc[Gg];
__device__ float g_beff[Gg];
__device__ float g_hn[Bb * Ll];
__device__ float g_cn[Bb * Ll];

// ------------------------- helpers -------------------------
__device__ __forceinline__ ull pk(float x, float y) {
    ull r; asm("mov.b64 %0, {%1, %2};" : "=l"(r) : "f"(x), "f"(y)); return r;
}
__device__ __forceinline__ void upk(ull v, float& x, float& y) {
    asm("mov.b64 {%0, %1}, %2;" : "=f"(x), "=f"(y) : "l"(v));
}
__device__ __forceinline__ void fma2(ull& d, ull a, ull b) {
    asm("fma.rn.f32x2 %0, %1, %2, %0;" : "+l"(d) : "l"(a), "l"(b));
}
__device__ __forceinline__ float ex2a(float x) {
    float r; asm("ex2.approx.f32 %0, %1;" : "=f"(r) : "f"(x)); return r;
}
__device__ __forceinline__ float rcpa(float x) {
    float r; asm("rcp.approx.f32 %0, %1;" : "=f"(r) : "f"(x)); return r;
}
__device__ __forceinline__ float fsig(float x) {
    return rcpa(1.0f + ex2a(-1.4426950408889634f * x));
}
__device__ __forceinline__ float ftanh(float x) {
    return fmaf(2.0f, rcpa(1.0f + ex2a(-2.8853900817779268f * x)), -1.0f);
}

// ------------------------- setup: fold decoder matrices -------------------------
__global__ void setup_kernel(const float* __restrict__ Wih_d,
                             const float* __restrict__ Whh_d,
                             const float* __restrict__ bih_d,
                             const float* __restrict__ bhh_d,
                             const float* __restrict__ Wdn,
                             const float* __restrict__ bdn,
                             const float* __restrict__ bih_e,
                             const float* __restrict__ bhh_e) {
    int j = blockIdx.x;   // gate 0..511
    int k = threadIdx.x;  // latent 0..127
    float s = 0.0f;
    for (int m = 0; m < Ff; m++) s += Wih_d[j * Ff + m] * Wdn[m * Ll + k];
    g_weff[j * Ll + k] = Whh_d[j * Ll + k] + s;
    if (k == 0) {
        float bs = bih_d[j] + bhh_d[j];
        for (int m = 0; m < Ff; m++) bs += Wih_d[j * Ff + m] * bdn[m];
        g_beff[j] = bs;
        g_benc[j] = bih_e[j] + bhh_e[j];
    }
}

// ------------------------- x-projection GEMM -------------------------
// Slot layout: slot s = l*4 + gi  <->  gate row gi*128 + l  (natural order i,f,g,o)
__global__ void __launch_bounds__(256, 1)
xproj_kernel(const float* __restrict__ x, const float* __restrict__ Wih) {
    extern __shared__ char smraw[];
    ulonglong2* Wsm = (ulonglong2*)smraw;            // [16][512] float4 = 128KB
    float* xs = (float*)(smraw + 16 * 512 * 16);     // [32][64] = 8KB
    const int t_ = threadIdx.x;
    const int sA = t_, sB = t_ + 256;
    const int gA = (sA & 3) * Ll + (sA >> 2);
    const int gB = (sB & 3) * Ll + (sB >> 2);

    const float4* wa = (const float4*)(Wih + gA * Ff);
    const float4* wb = (const float4*)(Wih + gB * Ff);
#pragma unroll
    for (int kg = 0; kg < 16; kg++) {
        ((float4*)Wsm)[kg * 512 + sA] = wa[kg];
        ((float4*)Wsm)[kg * 512 + sB] = wb[kg];
    }
    const float bA = g_benc[gA], bB = g_benc[gB];
    const size_t row0 = (size_t)blockIdx.x * 32;

    ((float4*)xs)[t_]       = ((const float4*)x)[row0 * 16 + t_];
    ((float4*)xs)[t_ + 256] = ((const float4*)x)[row0 * 16 + t_ + 256];
    __syncthreads();

    ull aA[32], aB[32];
#pragma unroll
    for (int r = 0; r < 32; r++) { aA[r] = 0ull; aB[r] = 0ull; }

#pragma unroll 4
    for (int kg = 0; kg < 16; kg++) {
        ulonglong2 wAv = Wsm[kg * 512 + sA];
        ulonglong2 wBv = Wsm[kg * 512 + sB];
#pragma unroll
        for (int r = 0; r < 32; r++) {
            ulonglong2 hh = *(const ulonglong2*)(xs + r * Ff + 4 * kg);
            fma2(aA[r], hh.x, wAv.x); fma2(aA[r], hh.y, wAv.y);
            fma2(aB[r], hh.x, wBv.x); fma2(aB[r], hh.y, wBv.y);
        }
    }
#pragma unroll
    for (int r = 0; r < 32; r++) {
        float lo, hi;
        upk(aA[r], lo, hi); g_gx[(row0 + r) * Gg + sA] = lo + hi + bA;
        upk(aB[r], lo, hi); g_gx[(row0 + r) * Gg + sB] = lo + hi + bB;
    }
}

// ------------------------- recurrent kernels -------------------------
// 512 threads; tid = l*4 + ks. Thread owns all 4 gates of latent l, all 4 batch
// rows, K-slice [32ks, 32ks+32). Partial sums reduced across the 4 ks-lanes via
// a 12-shfl butterfly that leaves row r = ks complete on lane ks; cell update is
// then fully thread-local (c in register, no gate exchange). 1 barrier/step via
// double-buffered h. W: CRS floats/gate/slice in regs, 24 in smem [ks][kk][gi][l]
// (fully lane-distinct loads). h smem sliced (SLICE=36) for conflict-free LDS.

// shared body via macro-free duplication for clarity

__global__ void __launch_bounds__(512, 1)
enc_kernel(const float* __restrict__ Whh) {
    extern __shared__ char smraw[];
    float4* Wsm = (float4*)smraw;                        // 4*NKK*4*128 float4 = 196608 B
    float* hs = (float*)(smraw + 4 * NKK * 4 * Ll * 16); // [2][4][HP]
    const int tid = threadIdx.x;
    const int l = tid >> 2, ks = tid & 3;
    const int b0 = blockIdx.x * BT;

    // register W: per gate, K [32ks, 32ks+CRS)
    ull Wr[4][CRS / 2];
#pragma unroll
    for (int gi = 0; gi < 4; gi++) {
        const float* wrow = Whh + (gi * Ll + l) * Ll + 32 * ks;
#pragma unroll
        for (int q = 0; q < CRS / 4; q++) {
            float4 v = *(const float4*)(wrow + 4 * q);
            Wr[gi][2 * q] = pk(v.x, v.y); Wr[gi][2 * q + 1] = pk(v.z, v.w);
        }
#pragma unroll
        for (int kk = 0; kk < NKK; kk++)
            Wsm[((ks * NKK + kk) * 4 + gi) * Ll + l] =
                *(const float4*)(wrow + CRS + 4 * kk);
    }
    // init h buffer 0 (thread writes its (row ks, latent l) slot)
    hs[ks * HP + (l >> 5) * SLICE + (l & 31)] = 0.0f;
    float c = 0.0f, hnew = 0.0f;
    __syncthreads();

    for (int t = 0; t < Ss; t++) {
        float4 gx = *(const float4*)(g_gx + ((size_t)(b0 + ks) * Ss + t) * Gg + 4 * l);
        const float* h = hs + (t & 1) * (4 * HP);
        ull acc[4][4];
#pragma unroll
        for (int gi = 0; gi < 4; gi++)
#pragma unroll
            for (int r = 0; r < 4; r++) acc[gi][r] = 0ull;
        // register half
#pragma unroll
        for (int r = 0; r < 4; r++) {
            const float* hb = h + r * HP + ks * SLICE;
#pragma unroll
            for (int q = 0; q < CRS / 4; q++) {
                ulonglong2 hh = *(const ulonglong2*)(hb + 4 * q);
#pragma unroll
                for (int gi = 0; gi < 4; gi++) {
                    fma2(acc[gi][r], hh.x, Wr[gi][2 * q]);
                    fma2(acc[gi][r], hh.y, Wr[gi][2 * q + 1]);
                }
            }
        }
        // smem half
#pragma unroll
        for (int kk = 0; kk < NKK; kk++) {
            ulonglong2 w0 = *(const ulonglong2*)&Wsm[((ks * NKK + kk) * 4 + 0) * Ll + l];
            ulonglong2 w1 = *(const ulonglong2*)&Wsm[((ks * NKK + kk) * 4 + 1) * Ll + l];
            ulonglong2 w2 = *(const ulonglong2*)&Wsm[((ks * NKK + kk) * 4 + 2) * Ll + l];
            ulonglong2 w3 = *(const ulonglong2*)&Wsm[((ks * NKK + kk) * 4 + 3) * Ll + l];
#pragma unroll
            for (int r = 0; r < 4; r++) {
                ulonglong2 hh = *(const ulonglong2*)(h + r * HP + ks * SLICE + CRS + 4 * kk);
                fma2(acc[0][r], hh.x, w0.x); fma2(acc[0][r], hh.y, w0.y);
                fma2(acc[1][r], hh.x, w1.x); fma2(acc[1][r], hh.y, w1.y);
                fma2(acc[2][r], hh.x, w2.x); fma2(acc[2][r], hh.y, w2.y);
                fma2(acc[3][r], hh.x, w3.x); fma2(acc[3][r], hh.y, w3.y);
            }
        }
        // reduce across ks-quad: lane ks ends with row r = ks for all 4 gates
        float red[4];
        const bool k0 = (ks & 1), k1 = (ks & 2);
#pragma unroll
        for (int gi = 0; gi < 4; gi++) {
            float lo, hi, v0, v1, v2, v3;
            upk(acc[gi][0], lo, hi); v0 = lo + hi;
            upk(acc[gi][1], lo, hi); v1 = lo + hi;
            upk(acc[gi][2], lo, hi); v2 = lo + hi;
            upk(acc[gi][3], lo, hi); v3 = lo + hi;
            float s_lo = k0 ? v0 : v1;
            float s_hi = k0 ? v2 : v3;
            float a = (k0 ? v1 : v0) + __shfl_xor_sync(0xffffffffu, s_lo, 1);
            float b = (k0 ? v3 : v2) + __shfl_xor_sync(0xffffffffu, s_hi, 1);
            float snd = k1 ? a : b;
            float kep = k1 ? b : a;
            red[gi] = kep + __shfl_xor_sync(0xffffffffu, snd, 2);
        }
        float vi = red[0] + gx.x;
        float vf = red[1] + gx.y;
        float vg = red[2] + gx.z;
        float vo = red[3] + gx.w;
        c = fsig(vf) * c + fsig(vi) * ftanh(vg);
        hnew = fsig(vo) * ftanh(c);
        hs[((t + 1) & 1) * (4 * HP) + ks * HP + (l >> 5) * SLICE + (l & 31)] = hnew;
        __syncthreads();
    }
    g_hn[(b0 + ks) * Ll + l] = hnew;
    g_cn[(b0 + ks) * Ll + l] = c;
}

__global__ void __launch_bounds__(512, 1)
dec_kernel() {
    extern __shared__ char smraw[];
    float4* Wsm = (float4*)smraw;
    float* hs = (float*)(smraw + 4 * NKK * 4 * Ll * 16);
    const int tid = threadIdx.x;
    const int l = tid >> 2, ks = tid & 3;
    const int b0 = blockIdx.x * BT;

    ull Wr[4][CRS / 2];
    float be[4];
#pragma unroll
    for (int gi = 0; gi < 4; gi++) {
        const float* wrow = g_weff + (gi * Ll + l) * Ll + 32 * ks;
#pragma unroll
        for (int q = 0; q < CRS / 4; q++) {
            float4 v = *(const float4*)(wrow + 4 * q);
            Wr[gi][2 * q] = pk(v.x, v.y); Wr[gi][2 * q + 1] = pk(v.z, v.w);
        }
#pragma unroll
        for (int kk = 0; kk < NKK; kk++)
            Wsm[((ks * NKK + kk) * 4 + gi) * Ll + l] =
                *(const float4*)(wrow + CRS + 4 * kk);
        be[gi] = g_beff[gi * Ll + l];
    }
    float c = g_cn[(b0 + ks) * Ll + l];
    hs[ks * HP + (l >> 5) * SLICE + (l & 31)] = g_hn[(b0 + ks) * Ll + l];
    __syncthreads();

    float* hout = g_hall + ((size_t)(b0 + ks) * Ss) * Ll + l;
    for (int t = 0; t < Ss; t++) {
        const float* h = hs + (t & 1) * (4 * HP);
        ull acc[4][4];
#pragma unroll
        for (int gi = 0; gi < 4; gi++)
#pragma unroll
            for (int r = 0; r < 4; r++) acc[gi][r] = 0ull;
#pragma unroll
        for (int r = 0; r < 4; r++) {
            const float* hb = h + r * HP + ks * SLICE;
#pragma unroll
            for (int q = 0; q < CRS / 4; q++) {
                ulonglong2 hh = *(const ulonglong2*)(hb + 4 * q);
#pragma unroll
                for (int gi = 0; gi < 4; gi++) {
                    fma2(acc[gi][r], hh.x, Wr[gi][2 * q]);
                    fma2(acc[gi][r], hh.y, Wr[gi][2 * q + 1]);
                }
            }
        }
#pragma unroll
        for (int kk = 0; kk < NKK; kk++) {
            ulonglong2 w0 = *(const ulonglong2*)&Wsm[((ks * NKK + kk) * 4 + 0) * Ll + l];
            ulonglong2 w1 = *(const ulonglong2*)&Wsm[((ks * NKK + kk) * 4 + 1) * Ll + l];
            ulonglong2 w2 = *(const ulonglong2*)&Wsm[((ks * NKK + kk) * 4 + 2) * Ll + l];
            ulonglong2 w3 = *(const ulonglong2*)&Wsm[((ks * NKK + kk) * 4 + 3) * Ll + l];
#pragma unroll
            for (int r = 0; r < 4; r++) {
                ulonglong2 hh = *(const ulonglong2*)(h + r * HP + ks * SLICE + CRS + 4 * kk);
                fma2(acc[0][r], hh.x, w0.x); fma2(acc[0][r], hh.y, w0.y);
                fma2(acc[1][r], hh.x, w1.x); fma2(acc[1][r], hh.y, w1.y);
                fma2(acc[2][r], hh.x, w2.x); fma2(acc[2][r], hh.y, w2.y);
                fma2(acc[3][r], hh.x, w3.x); fma2(acc[3][r], hh.y, w3.y);
            }
        }
        float red[4];
        const bool k0 = (ks & 1), k1 = (ks & 2);
#pragma unroll
        for (int gi = 0; gi < 4; gi++) {
            float lo, hi, v0, v1, v2, v3;
            upk(acc[gi][0], lo, hi); v0 = lo + hi;
            upk(acc[gi][1], lo, hi); v1 = lo + hi;
            upk(acc[gi][2], lo, hi); v2 = lo + hi;
            upk(acc[gi][3], lo, hi); v3 = lo + hi;
            float s_lo = k0 ? v0 : v1;
            float s_hi = k0 ? v2 : v3;
            float a = (k0 ? v1 : v0) + __shfl_xor_sync(0xffffffffu, s_lo, 1);
            float b = (k0 ? v3 : v2) + __shfl_xor_sync(0xffffffffu, s_hi, 1);
            float snd = k1 ? a : b;
            float kep = k1 ? b : a;
            red[gi] = kep + __shfl_xor_sync(0xffffffffu, snd, 2);
        }
        float vi = red[0] + be[0];
        float vf = red[1] + be[1];
        float vg = red[2] + be[2];
        float vo = red[3] + be[3];
        c = fsig(vf) * c + fsig(vi) * ftanh(vg);
        float hnew = fsig(vo) * ftanh(c);
        hs[((t + 1) & 1) * (4 * HP) + ks * HP + (l >> 5) * SLICE + (l & 31)] = hnew;
        hout[(size_t)t * Ll] = hnew;   // g_hall[b][t][l] = H_{t+1}
        __syncthreads();
    }
}

// ------------------------- output GEMM + flip -------------------------
__global__ void __launch_bounds__(256, 1)
out_kernel(const float* __restrict__ Wdn, const float* __restrict__ bdn,
           float* __restrict__ out) {
    extern __shared__ float hsm[];   // [128][128] = 64KB
    const int tid = threadIdx.x;
    const size_t row0 = (size_t)blockIdx.x * 128;
    for (int i = tid; i < 128 * Ll / 4; i += 256)
        ((float4*)hsm)[i] = ((const float4*)g_hall)[row0 * (Ll / 4) + i];

    const int f = tid & 63, rg = tid >> 6;
    ull Wd[64];
    const float4* wd = (const float4*)(Wdn + f * Ll);
#pragma unroll
    for (int q = 0; q < 32; q++) {
        float4 v = wd[q];
        Wd[2 * q] = pk(v.x, v.y); Wd[2 * q + 1] = pk(v.z, v.w);
    }
    const float bv = bdn[f];
    __syncthreads();

#pragma unroll 1
    for (int rr = 0; rr < 32; rr += 2) {
        int row = rg * 32 + rr;
        ull a0 = 0, a1 = 0;
#pragma unroll
        for (int q = 0; q < 32; q++) {
            ulonglong2 h0 = *(const ulonglong2*)(hsm + row * Ll + 4 * q);
            ulonglong2 h1 = *(const ulonglong2*)(hsm + (row + 1) * Ll + 4 * q);
            fma2(a0, h0.x, Wd[2 * q]); fma2(a0, h0.y, Wd[2 * q + 1]);
            fma2(a1, h1.x, Wd[2 * q]); fma2(a1, h1.y, Wd[2 * q + 1]);
        }
        float lo, hi;
        upk(a0, lo, hi); float s0 = lo + hi + bv;
        upk(a1, lo, hi); float s1 = lo + hi + bv;
        size_t g0 = row0 + row;
        size_t b_ = g0 >> 10; int t_ = (int)(g0 & 1023);
        out[(b_ * Ss + (size_t)(Ss - 1 - t_)) * Ff + f] = s0;
        g0 += 1;
        b_ = g0 >> 10; t_ = (int)(g0 & 1023);
        out[(b_ * Ss + (size_t)(Ss - 1 - t_)) * Ff + f] = s1;
    }
}

// ------------------------- launch -------------------------
extern "C" void kernel_launch(void* const* d_in, const int* in_sizes, int n_in,
                              void* d_out, int out_size) {
    const float* x     = (const float*)d_in[0];
    const float* Wih_e = (const float*)d_in[1];
    const float* Whh_e = (const float*)d_in[2];
    const float* bih_e = (const float*)d_in[3];
    const float* bhh_e = (const float*)d_in[4];
    const float* Wih_d = (const float*)d_in[5];
    const float* Whh_d = (const float*)d_in[6];
    const float* bih_d = (const float*)d_in[7];
    const float* bhh_d = (const float*)d_in[8];
    const float* Wdn   = (const float*)d_in[9];
    const float* bdn   = (const float*)d_in[10];
    float* out = (float*)d_out;

    const int SM_X = 16 * 512 * 16 + 32 * 64 * 4;              // 139264
    const int SM_R = 4 * NKK * 4 * Ll * 16 + 2 * 4 * HP * 4;   // 196608 + 4736 = 201344
    const int SM_O = 128 * Ll * 4;                             // 65536

    cudaFuncSetAttribute(xproj_kernel, cudaFuncAttributeMaxDynamicSharedMemorySize, SM_X);
    cudaFuncSetAttribute(enc_kernel,   cudaFuncAttributeMaxDynamicSharedMemorySize, SM_R);
    cudaFuncSetAttribute(dec_kernel,   cudaFuncAttributeMaxDynamicSharedMemorySize, SM_R);
    cudaFuncSetAttribute(out_kernel,   cudaFuncAttributeMaxDynamicSharedMemorySize, SM_O);

    setup_kernel<<<Gg, Ll>>>(Wih_d, Whh_d, bih_d, bhh_d, Wdn, bdn, bih_e, bhh_e);
    xproj_kernel<<<(Bb * Ss) / 32, 256, SM_X>>>(x, Wih_e);
    enc_kernel<<<Bb / BT, 512, SM_R>>>(Whh_e);
    dec_kernel<<<Bb / BT, 512, SM_R>>>();
    out_kernel<<<(Bb * Ss) / 128, 256, SM_O>>>(Wdn, bdn, out);
}

// round 11
// speedup vs baseline: 1.4103x; 1.4103x over previous
#include <cuda_runtime.h>

// Problem constants
#define Bb 512
#define Ss 1024
#define Ff 64
#define Ll 128
#define Gg 512    // 4*L
#define BT 4      // batch rows per CTA
#define CRg 88    // W cols per gate in registers (44 f32x2 k-pairs)
#define NWC 10    // W smem float4 chunks per gate (40 cols)
#define HBUF 132  // float4 stride of one h buffer (128 used + 4 pad)

typedef unsigned long long ull;

// ------------------------- device scratch -------------------------
__device__ float g_gx[(size_t)Bb * Ss * Gg];    // x-proj + enc bias, natural [row][gate] (1 GB)
__device__ float g_hall[(size_t)Bb * Ss * Ll];  // decoder h states (256 MB)
__device__ float g_weff[Gg * Ll];               // W_hh_dec + W_ih_dec @ W_dense
__device__ float g_benc[Gg];
__device__ float g_beff[Gg];
__device__ float g_hn[Bb * Ll];
__device__ float g_cn[Bb * Ll];

// ------------------------- helpers -------------------------
__device__ __forceinline__ ull pk(float x, float y) {
    ull r; asm("mov.b64 %0, {%1, %2};" : "=l"(r) : "f"(x), "f"(y)); return r;
}
__device__ __forceinline__ void upk(ull v, float& x, float& y) {
    asm("mov.b64 {%0, %1}, %2;" : "=f"(x), "=f"(y) : "l"(v));
}
__device__ __forceinline__ void fma2(ull& d, ull a, ull b) {
    asm("fma.rn.f32x2 %0, %1, %2, %0;" : "+l"(d) : "l"(a), "l"(b));
}
__device__ __forceinline__ float ex2a(float x) {
    float r; asm("ex2.approx.f32 %0, %1;" : "=f"(r) : "f"(x)); return r;
}
__device__ __forceinline__ float rcpa(float x) {
    float r; asm("rcp.approx.f32 %0, %1;" : "=f"(r) : "f"(x)); return r;
}
__device__ __forceinline__ float fsig(float x) {
    return rcpa(1.0f + ex2a(-1.4426950408889634f * x));
}
__device__ __forceinline__ float ftanh(float x) {
    return fmaf(2.0f, rcpa(1.0f + ex2a(-2.8853900817779268f * x)), -1.0f);
}

// h buffer float index for value h[k][r] (interleaved for broadcast pair loads):
// float4 slot (k>>1)*2 + (r>>1) holds {h[2k2][r0], h[2k2+1][r0], h[2k2][r0+1], h[2k2+1][r0+1]}
__device__ __forceinline__ int hidx(int k, int r) {
    return ((k >> 1) * 2 + (r >> 1)) * 4 + (r & 1) * 2 + (k & 1);
}

// ------------------------- setup: fold decoder matrices -------------------------
__global__ void setup_kernel(const float* __restrict__ Wih_d,
                             const float* __restrict__ Whh_d,
                             const float* __restrict__ bih_d,
                             const float* __restrict__ bhh_d,
                             const float* __restrict__ Wdn,
                             const float* __restrict__ bdn,
                             const float* __restrict__ bih_e,
                             const float* __restrict__ bhh_e) {
    int j = blockIdx.x;   // gate 0..511
    int k = threadIdx.x;  // latent 0..127
    float s = 0.0f;
    for (int m = 0; m < Ff; m++) s += Wih_d[j * Ff + m] * Wdn[m * Ll + k];
    g_weff[j * Ll + k] = Whh_d[j * Ll + k] + s;
    if (k == 0) {
        float bs = bih_d[j] + bhh_d[j];
        for (int m = 0; m < Ff; m++) bs += Wih_d[j * Ff + m] * bdn[m];
        g_beff[j] = bs;
        g_benc[j] = bih_e[j] + bhh_e[j];
    }
}

// ------------------------- x-projection GEMM -------------------------
// gx[row][j] = b_enc[j] + x[row,:] @ W_ih_enc[j,:]   (natural gate order)
__global__ void __launch_bounds__(256, 1)
xproj_kernel(const float* __restrict__ x, const float* __restrict__ Wih) {
    extern __shared__ char smraw[];
    ulonglong2* Wsm = (ulonglong2*)smraw;            // [16][512] float4 = 128KB
    float* xs = (float*)(smraw + 16 * 512 * 16);     // [32][64] = 8KB
    const int t_ = threadIdx.x;
    const int gA = t_, gB = t_ + 256;

    const float4* wa = (const float4*)(Wih + gA * Ff);
    const float4* wb = (const float4*)(Wih + gB * Ff);
#pragma unroll
    for (int kg = 0; kg < 16; kg++) {
        ((float4*)Wsm)[kg * 512 + gA] = wa[kg];
        ((float4*)Wsm)[kg * 512 + gB] = wb[kg];
    }
    const float bA = g_benc[gA], bB = g_benc[gB];
    const size_t row0 = (size_t)blockIdx.x * 32;

    ((float4*)xs)[t_]       = ((const float4*)x)[row0 * 16 + t_];
    ((float4*)xs)[t_ + 256] = ((const float4*)x)[row0 * 16 + t_ + 256];
    __syncthreads();

    ull aA[32], aB[32];
#pragma unroll
    for (int r = 0; r < 32; r++) { aA[r] = 0ull; aB[r] = 0ull; }

#pragma unroll 4
    for (int kg = 0; kg < 16; kg++) {
        ulonglong2 wAv = Wsm[kg * 512 + gA];
        ulonglong2 wBv = Wsm[kg * 512 + gB];
#pragma unroll
        for (int r = 0; r < 32; r++) {
            ulonglong2 hh = *(const ulonglong2*)(xs + r * Ff + 4 * kg);
            fma2(aA[r], hh.x, wAv.x); fma2(aA[r], hh.y, wAv.y);
            fma2(aB[r], hh.x, wBv.x); fma2(aB[r], hh.y, wBv.y);
        }
    }
#pragma unroll
    for (int r = 0; r < 32; r++) {
        float lo, hi;
        upk(aA[r], lo, hi); g_gx[(row0 + r) * Gg + gA] = lo + hi + bA;
        upk(aB[r], lo, hi); g_gx[(row0 + r) * Gg + gB] = lo + hi + bB;
    }
}

// ------------------------- recurrent kernels -------------------------
// 512 threads. Phase 1: thread j computes gate j for all 4 rows.
//   W row j: k<CRg in registers, rest from Wsm[ch][j] (lane-distinct, coalesced).
//   h read via WARP-UNIFORM broadcast LDS.128 from interleaved double buffer.
//   Accumulators are f32x2 over k-parity; gate value written to gs[r][j].
// Phase 2: thread (l = tid&127, r = tid>>7) does the cell update; c in register.
// Two barriers per step.

__global__ void __launch_bounds__(512, 1)
enc_kernel(const float* __restrict__ Whh) {
    extern __shared__ char smraw[];
    float4* Wsm = (float4*)smraw;                            // NWC*512 float4 = 80KB
    float4* hf4 = (float4*)(smraw + NWC * 512 * 16);         // [2][HBUF] float4
    float* gs = (float*)(smraw + NWC * 512 * 16 + 2 * HBUF * 16);  // [4][512]
    const int j = threadIdx.x;
    const int l = j & 127, r = j >> 7;
    const int b0 = blockIdx.x * BT;

    ull Wr[CRg / 2];
    {
        const float4* wrow = (const float4*)(Whh + j * Ll);
#pragma unroll
        for (int q = 0; q < CRg / 4; q++) {
            float4 v = wrow[q];
            Wr[2 * q] = pk(v.x, v.y); Wr[2 * q + 1] = pk(v.z, v.w);
        }
#pragma unroll
        for (int ch = 0; ch < NWC; ch++)
            Wsm[ch * 512 + j] = wrow[CRg / 4 + ch];
    }
    // zero h buffer 0 (thread (l,r) owns slot (k=l, r))
    ((float*)hf4)[hidx(l, r)] = 0.0f;
    float c = 0.0f, hn = 0.0f;
    __syncthreads();

    for (int t = 0; t < Ss; t++) {
        float gxv[BT];
#pragma unroll
        for (int rr = 0; rr < BT; rr++)
            gxv[rr] = g_gx[((size_t)(b0 + rr) * Ss + t) * Gg + j];
        const float4* hb = hf4 + (t & 1) * HBUF;
        ull a0 = 0, a1 = 0, a2 = 0, a3 = 0;
        // register W part: k-pairs 0..CRg/2
#pragma unroll
        for (int k2 = 0; k2 < CRg / 2; k2++) {
            ulonglong2 h01 = *(const ulonglong2*)(hb + 2 * k2);      // rows 0,1
            ulonglong2 h23 = *(const ulonglong2*)(hb + 2 * k2 + 1);  // rows 2,3
            fma2(a0, h01.x, Wr[k2]); fma2(a1, h01.y, Wr[k2]);
            fma2(a2, h23.x, Wr[k2]); fma2(a3, h23.y, Wr[k2]);
        }
        // smem W part: NWC chunks of 2 k-pairs
#pragma unroll
        for (int ch = 0; ch < NWC; ch++) {
            ulonglong2 wv = *(const ulonglong2*)(Wsm + ch * 512 + j);
            int k2 = CRg / 2 + 2 * ch;
            ulonglong2 h01 = *(const ulonglong2*)(hb + 2 * k2);
            ulonglong2 h23 = *(const ulonglong2*)(hb + 2 * k2 + 1);
            fma2(a0, h01.x, wv.x); fma2(a1, h01.y, wv.x);
            fma2(a2, h23.x, wv.x); fma2(a3, h23.y, wv.x);
            h01 = *(const ulonglong2*)(hb + 2 * k2 + 2);
            h23 = *(const ulonglong2*)(hb + 2 * k2 + 3);
            fma2(a0, h01.x, wv.y); fma2(a1, h01.y, wv.y);
            fma2(a2, h23.x, wv.y); fma2(a3, h23.y, wv.y);
        }
        float lo, hi;
        upk(a0, lo, hi); gs[0 * 512 + j] = lo + hi + gxv[0];
        upk(a1, lo, hi); gs[1 * 512 + j] = lo + hi + gxv[1];
        upk(a2, lo, hi); gs[2 * 512 + j] = lo + hi + gxv[2];
        upk(a3, lo, hi); gs[3 * 512 + j] = lo + hi + gxv[3];
        __syncthreads();
        // cell update for (l, r)
        {
            float vi = gs[r * 512 + l];
            float vf = gs[r * 512 + 128 + l];
            float vg = gs[r * 512 + 256 + l];
            float vo = gs[r * 512 + 384 + l];
            c = fsig(vf) * c + fsig(vi) * ftanh(vg);
            hn = fsig(vo) * ftanh(c);
            ((float*)(hf4 + ((t + 1) & 1) * HBUF))[hidx(l, r)] = hn;
        }
        __syncthreads();
    }
    g_hn[(b0 + r) * Ll + l] = hn;
    g_cn[(b0 + r) * Ll + l] = c;
}

__global__ void __launch_bounds__(512, 1)
dec_kernel() {
    extern __shared__ char smraw[];
    float4* Wsm = (float4*)smraw;
    float4* hf4 = (float4*)(smraw + NWC * 512 * 16);
    float* gs = (float*)(smraw + NWC * 512 * 16 + 2 * HBUF * 16);
    const int j = threadIdx.x;
    const int l = j & 127, r = j >> 7;
    const int b0 = blockIdx.x * BT;

    ull Wr[CRg / 2];
    {
        const float4* wrow = (const float4*)(g_weff + j * Ll);
#pragma unroll
        for (int q = 0; q < CRg / 4; q++) {
            float4 v = wrow[q];
            Wr[2 * q] = pk(v.x, v.y); Wr[2 * q + 1] = pk(v.z, v.w);
        }
#pragma unroll
        for (int ch = 0; ch < NWC; ch++)
            Wsm[ch * 512 + j] = wrow[CRg / 4 + ch];
    }
    const float be = g_beff[j];
    ((float*)hf4)[hidx(l, r)] = g_hn[(b0 + r) * Ll + l];
    float c = g_cn[(b0 + r) * Ll + l];
    float* hout = g_hall + ((size_t)(b0 + r) * Ss) * Ll + l;
    __syncthreads();

    for (int t = 0; t < Ss; t++) {
        const float4* hb = hf4 + (t & 1) * HBUF;
        ull a0 = 0, a1 = 0, a2 = 0, a3 = 0;
#pragma unroll
        for (int k2 = 0; k2 < CRg / 2; k2++) {
            ulonglong2 h01 = *(const ulonglong2*)(hb + 2 * k2);
            ulonglong2 h23 = *(const ulonglong2*)(hb + 2 * k2 + 1);
            fma2(a0, h01.x, Wr[k2]); fma2(a1, h01.y, Wr[k2]);
            fma2(a2, h23.x, Wr[k2]); fma2(a3, h23.y, Wr[k2]);
        }
#pragma unroll
        for (int ch = 0; ch < NWC; ch++) {
            ulonglong2 wv = *(const ulonglong2*)(Wsm + ch * 512 + j);
            int k2 = CRg / 2 + 2 * ch;
            ulonglong2 h01 = *(const ulonglong2*)(hb + 2 * k2);
            ulonglong2 h23 = *(const ulonglong2*)(hb + 2 * k2 + 1);
            fma2(a0, h01.x, wv.x); fma2(a1, h01.y, wv.x);
            fma2(a2, h23.x, wv.x); fma2(a3, h23.y, wv.x);
            h01 = *(const ulonglong2*)(hb + 2 * k2 + 2);
            h23 = *(const ulonglong2*)(hb + 2 * k2 + 3);
            fma2(a0, h01.x, wv.y); fma2(a1, h01.y, wv.y);
            fma2(a2, h23.x, wv.y); fma2(a3, h23.y, wv.y);
        }
        float lo, hi;
        upk(a0, lo, hi); gs[0 * 512 + j] = lo + hi + be;
        upk(a1, lo, hi); gs[1 * 512 + j] = lo + hi + be;
        upk(a2, lo, hi); gs[2 * 512 + j] = lo + hi + be;
        upk(a3, lo, hi); gs[3 * 512 + j] = lo + hi + be;
        __syncthreads();
        {
            float vi = gs[r * 512 + l];
            float vf = gs[r * 512 + 128 + l];
            float vg = gs[r * 512 + 256 + l];
            float vo = gs[r * 512 + 384 + l];
            c = fsig(vf) * c + fsig(vi) * ftanh(vg);
            float hn = fsig(vo) * ftanh(c);
            ((float*)(hf4 + ((t + 1) & 1) * HBUF))[hidx(l, r)] = hn;
            hout[(size_t)t * Ll] = hn;   // g_hall[b][t][l] = H_{t+1}, coalesced
        }
        __syncthreads();
    }
}

// ------------------------- output GEMM + flip -------------------------
__global__ void __launch_bounds__(256, 1)
out_kernel(const float* __restrict__ Wdn, const float* __restrict__ bdn,
           float* __restrict__ out) {
    extern __shared__ float hsm[];   // [128][128] = 64KB
    const int tid = threadIdx.x;
    const size_t row0 = (size_t)blockIdx.x * 128;
    for (int i = tid; i < 128 * Ll / 4; i += 256)
        ((float4*)hsm)[i] = ((const float4*)g_hall)[row0 * (Ll / 4) + i];

    const int f = tid & 63, rg = tid >> 6;
    ull Wd[64];
    const float4* wd = (const float4*)(Wdn + f * Ll);
#pragma unroll
    for (int q = 0; q < 32; q++) {
        float4 v = wd[q];
        Wd[2 * q] = pk(v.x, v.y); Wd[2 * q + 1] = pk(v.z, v.w);
    }
    const float bv = bdn[f];
    __syncthreads();

#pragma unroll 1
    for (int rr = 0; rr < 32; rr += 2) {
        int row = rg * 32 + rr;
        ull a0 = 0, a1 = 0;
#pragma unroll
        for (int q = 0; q < 32; q++) {
            ulonglong2 h0 = *(const ulonglong2*)(hsm + row * Ll + 4 * q);
            ulonglong2 h1 = *(const ulonglong2*)(hsm + (row + 1) * Ll + 4 * q);
            fma2(a0, h0.x, Wd[2 * q]); fma2(a0, h0.y, Wd[2 * q + 1]);
            fma2(a1, h1.x, Wd[2 * q]); fma2(a1, h1.y, Wd[2 * q + 1]);
        }
        float lo, hi;
        upk(a0, lo, hi); float s0 = lo + hi + bv;
        upk(a1, lo, hi); float s1 = lo + hi + bv;
        size_t g0 = row0 + row;
        size_t b_ = g0 >> 10; int t_ = (int)(g0 & 1023);
        out[(b_ * Ss + (size_t)(Ss - 1 - t_)) * Ff + f] = s0;
        g0 += 1;
        b_ = g0 >> 10; t_ = (int)(g0 & 1023);
        out[(b_ * Ss + (size_t)(Ss - 1 - t_)) * Ff + f] = s1;
    }
}

// ------------------------- launch -------------------------
extern "C" void kernel_launch(void* const* d_in, const int* in_sizes, int n_in,
                              void* d_out, int out_size) {
    const float* x     = (const float*)d_in[0];
    const float* Wih_e = (const float*)d_in[1];
    const float* Whh_e = (const float*)d_in[2];
    const float* bih_e = (const float*)d_in[3];
    const float* bhh_e = (const float*)d_in[4];
    const float* Wih_d = (const float*)d_in[5];
    const float* Whh_d = (const float*)d_in[6];
    const float* bih_d = (const float*)d_in[7];
    const float* bhh_d = (const float*)d_in[8];
    const float* Wdn   = (const float*)d_in[9];
    const float* bdn   = (const float*)d_in[10];
    float* out = (float*)d_out;

    const int SM_X = 16 * 512 * 16 + 32 * 64 * 4;                 // 139264
    const int SM_R = NWC * 512 * 16 + 2 * HBUF * 16 + 4 * 512 * 4; // 81920+4224+8192 = 94336
    const int SM_O = 128 * Ll * 4;                                // 65536

    cudaFuncSetAttribute(xproj_kernel, cudaFuncAttributeMaxDynamicSharedMemorySize, SM_X);
    cudaFuncSetAttribute(enc_kernel,   cudaFuncAttributeMaxDynamicSharedMemorySize, SM_R);
    cudaFuncSetAttribute(dec_kernel,   cudaFuncAttributeMaxDynamicSharedMemorySize, SM_R);
    cudaFuncSetAttribute(out_kernel,   cudaFuncAttributeMaxDynamicSharedMemorySize, SM_O);

    setup_kernel<<<Gg, Ll>>>(Wih_d, Whh_d, bih_d, bhh_d, Wdn, bdn, bih_e, bhh_e);
    xproj_kernel<<<(Bb * Ss) / 32, 256, SM_X>>>(x, Wih_e);
    enc_kernel<<<Bb / BT, 512, SM_R>>>(Whh_e);
    dec_kernel<<<Bb / BT, 512, SM_R>>>();
    out_kernel<<<(Bb * Ss) / 128, 256, SM_O>>>(Wdn, bdn, out);
}